// round 3
// baseline (speedup 1.0000x reference)
#include <cuda_runtime.h>
#include <math.h>

#define NN 100000
#define EE 200000
#define H 128
#define NH (NN*H)
#define NGROUP 24   // 8 levels x 3 gate types (level 0 unused)

// ---------------- scratch (static device memory; no allocs) ----------------
__device__ float g_msg[NN*H];            // 51.2 MB message accumulator (zero at load; bucket rows re-zeroed per replay)
__device__ float g_hstype[6*H];          // per-gate-type hs row
__device__ float g_wihT[3][H*384];       // gru_wih transposed to [k][row]
__device__ int   g_ecnt[NGROUP];
__device__ int   g_ncnt[NGROUP];
__device__ int   g_ebuck[NGROUP][EE];    // edge ids per (level,gate) group
__device__ int   g_nbuck[NGROUP][NN];    // node ids per (level,gate) group

// ---------------- setup kernels ----------------
__global__ void zcnt_k() {
    int t = threadIdx.x;
    if (t < NGROUP) { g_ecnt[t] = 0; g_ncnt[t] = 0; }
}

// hs_type[g] = concat(Ws[g], Wt[g]) @ hs_W + hs_b   (6 x 128)
__global__ void hs_type_k(const float* __restrict__ Ws, const float* __restrict__ Wt,
                          const float* __restrict__ hsW, const float* __restrict__ hsb) {
    int g = blockIdx.x;      // 0..5
    int j = threadIdx.x;     // 0..127
    __shared__ float st[256];
    st[j]       = Ws[g*H + j];
    st[128 + j] = Wt[g*H + j];
    __syncthreads();
    float acc = hsb[j];
    #pragma unroll 8
    for (int k = 0; k < 256; k++) acc = fmaf(st[k], hsW[k*H + j], acc);
    g_hstype[g*H + j] = acc;
}

// transpose gru_wih [3][384][128] -> g_wihT [3][128][384]
__global__ void wihT_k(const float* __restrict__ wih) {
    int idx = blockIdx.x * blockDim.x + threadIdx.x;
    if (idx >= 3*384*H) return;
    int gi = idx / (384*H);
    int r  = idx % (384*H);
    int row = r / H;
    int k   = r % H;
    g_wihT[gi][k*384 + row] = wih[(size_t)gi*384*H + row*H + k];
}

// write hs rows, zero hf region (per replay). msg zeroed selectively by zmsg_k.
__global__ void scatter_k(const int* __restrict__ gate, float* __restrict__ out) {
    int j = threadIdx.x;
    for (int i = blockIdx.x; i < NN; i += gridDim.x) {
        int g = gate[i];
        out[i*H + j]        = g_hstype[g*H + j];
        out[NH + i*H + j]   = 0.f;
    }
}

__device__ __forceinline__ int gate_to_gi(int g) {
    // GATE_CODES = (3, 2, 5)
    return (g == 3) ? 0 : (g == 2) ? 1 : (g == 5) ? 2 : -1;
}

__global__ void bedge_k(const int* __restrict__ ei, const int* __restrict__ gate,
                        const int* __restrict__ lvl) {
    for (int e = blockIdx.x * blockDim.x + threadIdx.x; e < EE; e += gridDim.x * blockDim.x) {
        int d = ei[EE + e];
        int gi = gate_to_gi(gate[d]);
        int l = lvl[d];
        if (gi >= 0 && l >= 1) {
            int grp = l*3 + gi;
            int p = atomicAdd(&g_ecnt[grp], 1);
            g_ebuck[grp][p] = e;
        }
    }
}

__global__ void bnode_k(const int* __restrict__ gate, const int* __restrict__ lvl) {
    for (int i = blockIdx.x * blockDim.x + threadIdx.x; i < NN; i += gridDim.x * blockDim.x) {
        int gi = gate_to_gi(gate[i]);
        int l = lvl[i];
        if (gi >= 0 && l >= 1) {
            int grp = l*3 + gi;
            int p = atomicAdd(&g_ncnt[grp], 1);
            g_nbuck[grp][p] = i;
        }
    }
}

// zero g_msg rows ONLY for nodes that appear in a bucket (the only rows ever
// read or written). Runs after bnode_k. Saves ~29 MB/replay of dead zeroing.
__global__ void zmsg_k() {
    int j = threadIdx.x;               // 0..127
    for (int grp = 0; grp < NGROUP; grp++) {
        int cnt = g_ncnt[grp];
        for (int t = blockIdx.x; t < cnt; t += gridDim.x) {
            int node = g_nbuck[grp][t];
            g_msg[(size_t)node*H + j] = 0.f;
        }
    }
}

// ---------------- per-level edge MLP: msg += W3 relu(W2 relu(W1 x + b1) + b2) + b3 ----------------
#define ETILE 16
__global__ void __launch_bounds__(128) emlp_k(
    int level, const int* __restrict__ ei,
    const float* __restrict__ w1, const float* __restrict__ b1,
    const float* __restrict__ w2, const float* __restrict__ b2,
    const float* __restrict__ w3, const float* __restrict__ b3,
    const float* __restrict__ nodes)   // d_out: hs at 0, hf at NH
{
    __shared__ __align__(16) float sx[ETILE*256];
    __shared__ __align__(16) float sh1[ETILE*H];
    __shared__ __align__(16) float sh2[ETILE*H];
    __shared__ int ssrc[ETILE];
    __shared__ int sdst[ETILE];
    const int j = threadIdx.x;
    const float* hs = nodes;
    const float* hf = nodes + NH;

    for (int gi = 0; gi < 3; gi++) {
        const int grp = level*3 + gi;
        const int cnt = g_ecnt[grp];
        const int ntile = (cnt + ETILE - 1) / ETILE;
        const float* W1 = w1 + (size_t)gi*2*H*H;
        const float* W2 = w2 + (size_t)gi*H*H;
        const float* W3 = w3 + (size_t)gi*H*H;
        const float B1 = b1[gi*H + j];
        const float B2 = b2[gi*H + j];
        const float B3 = b3[gi*H + j];

        for (int tile = blockIdx.x; tile < ntile; tile += gridDim.x) {
            const int base = tile * ETILE;
            const int ne = min(ETILE, cnt - base);
            if (j < ETILE) {
                int e = g_ebuck[grp][base + (j < ne ? j : 0)];
                ssrc[j] = ei[e];
                sdst[j] = ei[EE + e];
            }
            __syncthreads();
            #pragma unroll
            for (int t = 0; t < ETILE; t++) {
                int s = ssrc[t];
                sx[t*256 + j]       = hs[s*H + j];
                sx[t*256 + 128 + j] = hf[s*H + j];
            }
            __syncthreads();

            float acc[ETILE];
            // layer 1: 256 -> 128, relu
            #pragma unroll
            for (int t = 0; t < ETILE; t++) acc[t] = B1;
            for (int k = 0; k < 256; k += 4) {
                float wa = W1[(k+0)*H + j];
                float wb = W1[(k+1)*H + j];
                float wc = W1[(k+2)*H + j];
                float wd = W1[(k+3)*H + j];
                #pragma unroll
                for (int t = 0; t < ETILE; t++) {
                    float4 xv = *reinterpret_cast<const float4*>(&sx[t*256 + k]);
                    acc[t] = fmaf(xv.x, wa, acc[t]);
                    acc[t] = fmaf(xv.y, wb, acc[t]);
                    acc[t] = fmaf(xv.z, wc, acc[t]);
                    acc[t] = fmaf(xv.w, wd, acc[t]);
                }
            }
            #pragma unroll
            for (int t = 0; t < ETILE; t++) sh1[t*H + j] = fmaxf(acc[t], 0.f);
            __syncthreads();

            // layer 2: 128 -> 128, relu
            #pragma unroll
            for (int t = 0; t < ETILE; t++) acc[t] = B2;
            for (int k = 0; k < H; k += 4) {
                float wa = W2[(k+0)*H + j];
                float wb = W2[(k+1)*H + j];
                float wc = W2[(k+2)*H + j];
                float wd = W2[(k+3)*H + j];
                #pragma unroll
                for (int t = 0; t < ETILE; t++) {
                    float4 xv = *reinterpret_cast<const float4*>(&sh1[t*H + k]);
                    acc[t] = fmaf(xv.x, wa, acc[t]);
                    acc[t] = fmaf(xv.y, wb, acc[t]);
                    acc[t] = fmaf(xv.z, wc, acc[t]);
                    acc[t] = fmaf(xv.w, wd, acc[t]);
                }
            }
            #pragma unroll
            for (int t = 0; t < ETILE; t++) sh2[t*H + j] = fmaxf(acc[t], 0.f);
            __syncthreads();

            // layer 3: 128 -> 128, linear, scatter-add
            #pragma unroll
            for (int t = 0; t < ETILE; t++) acc[t] = B3;
            for (int k = 0; k < H; k += 4) {
                float wa = W3[(k+0)*H + j];
                float wb = W3[(k+1)*H + j];
                float wc = W3[(k+2)*H + j];
                float wd = W3[(k+3)*H + j];
                #pragma unroll
                for (int t = 0; t < ETILE; t++) {
                    float4 xv = *reinterpret_cast<const float4*>(&sh2[t*H + k]);
                    acc[t] = fmaf(xv.x, wa, acc[t]);
                    acc[t] = fmaf(xv.y, wb, acc[t]);
                    acc[t] = fmaf(xv.z, wc, acc[t]);
                    acc[t] = fmaf(xv.w, wd, acc[t]);
                }
            }
            for (int t = 0; t < ne; t++)
                atomicAdd(&g_msg[(size_t)sdst[t]*H + j], acc[t]);
            __syncthreads();  // protect ssrc/sdst/sh2 before next tile
        }
    }
}

// ---------------- per-level GRU (h_old == 0, so whh path is just bhh bias) ----------------
#define NTILE 16
__global__ void __launch_bounds__(128) gru_k(
    int level,
    const float* __restrict__ bih, const float* __restrict__ bhh,
    float* __restrict__ hfout)
{
    __shared__ __align__(16) float sm[NTILE*H];
    __shared__ int snode[NTILE];
    const int j = threadIdx.x;

    for (int gi = 0; gi < 3; gi++) {
        const int grp = level*3 + gi;
        const int cnt = g_ncnt[grp];
        const int ntile = (cnt + NTILE - 1) / NTILE;
        const float* WT = g_wihT[gi];
        const float br = bih[gi*384 + j]       + bhh[gi*384 + j];
        const float bz = bih[gi*384 + 128 + j] + bhh[gi*384 + 128 + j];
        const float bn = bih[gi*384 + 256 + j];
        const float hn = bhh[gi*384 + 256 + j];

        for (int tile = blockIdx.x; tile < ntile; tile += gridDim.x) {
            const int base = tile * NTILE;
            const int nn = min(NTILE, cnt - base);
            if (j < NTILE) snode[j] = g_nbuck[grp][base + (j < nn ? j : 0)];
            __syncthreads();
            #pragma unroll
            for (int t = 0; t < NTILE; t++) sm[t*H + j] = g_msg[(size_t)snode[t]*H + j];
            __syncthreads();

            float ar[NTILE], az[NTILE], an[NTILE];
            #pragma unroll
            for (int t = 0; t < NTILE; t++) { ar[t] = 0.f; az[t] = 0.f; an[t] = 0.f; }
            for (int k = 0; k < H; k += 2) {
                float wr0 = WT[(k+0)*384 + j];
                float wz0 = WT[(k+0)*384 + 128 + j];
                float wn0 = WT[(k+0)*384 + 256 + j];
                float wr1 = WT[(k+1)*384 + j];
                float wz1 = WT[(k+1)*384 + 128 + j];
                float wn1 = WT[(k+1)*384 + 256 + j];
                #pragma unroll
                for (int t = 0; t < NTILE; t++) {
                    float2 mv = *reinterpret_cast<const float2*>(&sm[t*H + k]);
                    ar[t] = fmaf(mv.x, wr0, ar[t]);
                    az[t] = fmaf(mv.x, wz0, az[t]);
                    an[t] = fmaf(mv.x, wn0, an[t]);
                    ar[t] = fmaf(mv.y, wr1, ar[t]);
                    az[t] = fmaf(mv.y, wz1, az[t]);
                    an[t] = fmaf(mv.y, wn1, an[t]);
                }
            }
            #pragma unroll
            for (int t = 0; t < NTILE; t++) {
                if (t < nn) {
                    float r = 1.f / (1.f + expf(-(ar[t] + br)));
                    float z = 1.f / (1.f + expf(-(az[t] + bz)));
                    float nst = tanhf(an[t] + bn + r * hn);
                    hfout[(size_t)snode[t]*H + j] = (1.f - z) * nst;
                }
            }
            __syncthreads();
        }
    }
}

// ---------------- launch ----------------
extern "C" void kernel_launch(void* const* d_in, const int* in_sizes, int n_in,
                              void* d_out, int out_size) {
    const int*   gate = (const int*)d_in[0];
    const int*   lvl  = (const int*)d_in[1];
    const int*   ei   = (const int*)d_in[2];
    const float* Ws   = (const float*)d_in[3];
    const float* Wt   = (const float*)d_in[4];
    const float* hsW  = (const float*)d_in[5];
    const float* hsb  = (const float*)d_in[6];
    const float* w1   = (const float*)d_in[7];
    const float* b1   = (const float*)d_in[8];
    const float* w2   = (const float*)d_in[9];
    const float* b2   = (const float*)d_in[10];
    const float* w3   = (const float*)d_in[11];
    const float* b3   = (const float*)d_in[12];
    const float* wih  = (const float*)d_in[13];
    // d_in[14] = gru_whh: provably unused (h_old == 0 for every updated node)
    const float* bih  = (const float*)d_in[15];
    const float* bhh  = (const float*)d_in[16];
    float* out = (float*)d_out;   // [0, NH) = hs, [NH, 2NH) = hf

    zcnt_k<<<1, 32>>>();
    hs_type_k<<<6, 128>>>(Ws, Wt, hsW, hsb);
    wihT_k<<<(3*384*H + 255)/256, 256>>>(wih);
    scatter_k<<<4096, 128>>>(gate, out);
    bedge_k<<<512, 256>>>(ei, gate, lvl);
    bnode_k<<<256, 256>>>(gate, lvl);
    zmsg_k<<<2048, 128>>>();

    for (int level = 1; level < 8; level++) {
        emlp_k<<<896, 128>>>(level, ei, w1, b1, w2, b2, w3, b3, out);
        gru_k<<<512, 128>>>(level, bih, bhh, out + NH);
    }
}

// round 6
// speedup vs baseline: 2.1713x; 2.1713x over previous
#include <cuda_runtime.h>
#include <math.h>

#define NN 100000
#define EE 200000
#define H 128
#define NH (NN*H)
#define NGROUP 24   // 8 levels x 3 gate types (level 0 unused)

// ---------------- scratch (static device memory; no allocs) ----------------
__device__ float g_msg[NN*H];            // h2 accumulator (zero at load; bucket rows re-zeroed per replay)
__device__ float g_hstype[6*H];          // per-gate-type hs row
__device__ float g_t1[3*6*H];            // layer1 hs-part table: t1[gi][g] = hstype[g]@W1a + b1
__device__ float g_w3T[3][H*H];          // W3 transposed [j][k]
__device__ float g_W4[3][H*384];         // W4 = W3 @ wih^T, k-major [k][m]
__device__ float g_c3[3*384];            // c3 = b3 @ wih^T
__device__ int   g_deg[NN];              // per-dst in-group degree
__device__ int   g_ecnt[NGROUP];
__device__ int   g_ncnt[NGROUP];
__device__ int   g_ebuck[NGROUP][EE];
__device__ int   g_nbuck[NGROUP][NN];

// ---------------- setup kernels ----------------
__global__ void zcnt_k() {
    int t = threadIdx.x;
    if (t < NGROUP) { g_ecnt[t] = 0; g_ncnt[t] = 0; }
}

// hs_type[g] = concat(Ws[g], Wt[g]) @ hs_W + hs_b   (6 x 128)
__global__ void hs_type_k(const float* __restrict__ Ws, const float* __restrict__ Wt,
                          const float* __restrict__ hsW, const float* __restrict__ hsb) {
    int g = blockIdx.x;      // 0..5
    int j = threadIdx.x;     // 0..127
    __shared__ float st[256];
    st[j]       = Ws[g*H + j];
    st[128 + j] = Wt[g*H + j];
    __syncthreads();
    float acc = hsb[j];
    #pragma unroll 8
    for (int k = 0; k < 256; k++) acc = fmaf(st[k], hsW[k*H + j], acc);
    g_hstype[g*H + j] = acc;
}

// t1[gi][g][j] = b1[gi][j] + sum_k hstype[g][k] * w1[gi][k][j]  (hs rows 0..127)
__global__ void t1_k(const float* __restrict__ w1, const float* __restrict__ b1) {
    int g = blockIdx.x, gi = blockIdx.y, j = threadIdx.x;
    __shared__ float sh[H];
    sh[j] = g_hstype[g*H + j];
    __syncthreads();
    float acc = b1[gi*H + j];
    const float* W = w1 + (size_t)gi*2*H*H;
    #pragma unroll 8
    for (int k = 0; k < H; k++) acc = fmaf(sh[k], W[k*H + j], acc);
    g_t1[(gi*6 + g)*H + j] = acc;
}

__global__ void w3T_k(const float* __restrict__ w3) {
    int idx = blockIdx.x*blockDim.x + threadIdx.x;
    if (idx >= 3*H*H) return;
    int gi = idx / (H*H);
    int r  = idx % (H*H);
    int k = r / H, j = r % H;
    g_w3T[gi][j*H + k] = w3[(size_t)gi*H*H + k*H + j];
}

// W4[gi][k][m] = sum_j w3[gi][k][j] * wih[gi][m][j]   (block: 8 m-values, 128 threads over k)
__global__ void w4_k(const float* __restrict__ wih) {
    int gi = blockIdx.y;
    int m0 = blockIdx.x * 8;
    int k  = threadIdx.x;
    __shared__ float sw[8][H];
    #pragma unroll
    for (int mm = 0; mm < 8; mm++) sw[mm][k] = wih[((size_t)gi*384 + m0 + mm)*H + k];
    __syncthreads();
    float acc[8];
    #pragma unroll
    for (int mm = 0; mm < 8; mm++) acc[mm] = 0.f;
    for (int j = 0; j < H; j++) {
        float v = g_w3T[gi][j*H + k];   // coalesced
        #pragma unroll
        for (int mm = 0; mm < 8; mm++) acc[mm] = fmaf(v, sw[mm][j], acc[mm]);
    }
    #pragma unroll
    for (int mm = 0; mm < 8; mm++) g_W4[gi][k*384 + m0 + mm] = acc[mm];
}

// c3[gi][m] = sum_j b3[gi][j] * wih[gi][m][j]
__global__ void c3_k(const float* __restrict__ b3, const float* __restrict__ wih) {
    int gi = blockIdx.x, m = threadIdx.x;   // 384 threads
    __shared__ float sb[H];
    if (m < H) sb[m] = b3[gi*H + m];
    __syncthreads();
    float acc = 0.f;
    for (int j = 0; j < H; j++) acc = fmaf(sb[j], wih[((size_t)gi*384 + m)*H + j], acc);
    g_c3[gi*384 + m] = acc;
}

// write hs rows + zero hf (float4), zero g_deg (per replay)
__global__ void scatter_k(const int* __restrict__ gate, float* __restrict__ out) {
    int j = threadIdx.x;
    int r = j >> 5, c = j & 31;
    float4* out4 = (float4*)out;
    const float4* ht4 = (const float4*)g_hstype;
    float4 z4 = make_float4(0.f, 0.f, 0.f, 0.f);
    for (int i0 = blockIdx.x*4; i0 < NN; i0 += gridDim.x*4) {
        int i = i0 + r;
        if (i < NN) {
            int g = gate[i];
            out4[(size_t)i*32 + c]        = ht4[g*32 + c];
            out4[(size_t)(NN + i)*32 + c] = z4;
        }
    }
    for (int i = blockIdx.x*blockDim.x + j; i < NN; i += gridDim.x*blockDim.x)
        g_deg[i] = 0;
}

__device__ __forceinline__ int gate_to_gi(int g) {
    // GATE_CODES = (3, 2, 5)
    return (g == 3) ? 0 : (g == 2) ? 1 : (g == 5) ? 2 : -1;
}

__global__ void bedge_k(const int* __restrict__ ei, const int* __restrict__ gate,
                        const int* __restrict__ lvl) {
    for (int e = blockIdx.x*blockDim.x + threadIdx.x; e < EE; e += gridDim.x*blockDim.x) {
        int d = ei[EE + e];
        int gi = gate_to_gi(gate[d]);
        int l = lvl[d];
        if (gi >= 0 && l >= 1) {
            int grp = l*3 + gi;
            int p = atomicAdd(&g_ecnt[grp], 1);
            g_ebuck[grp][p] = e;
            atomicAdd(&g_deg[d], 1);
        }
    }
}

__global__ void bnode_k(const int* __restrict__ gate, const int* __restrict__ lvl) {
    for (int i = blockIdx.x*blockDim.x + threadIdx.x; i < NN; i += gridDim.x*blockDim.x) {
        int gi = gate_to_gi(gate[i]);
        int l = lvl[i];
        if (gi >= 0 && l >= 1) {
            int grp = l*3 + gi;
            int p = atomicAdd(&g_ncnt[grp], 1);
            g_nbuck[grp][p] = i;
        }
    }
}

// zero g_msg rows only for bucket nodes (the only rows ever touched)
__global__ void zmsg_k() {
    int j = threadIdx.x;
    for (int grp = 0; grp < NGROUP; grp++) {
        int cnt = g_ncnt[grp];
        for (int t = blockIdx.x; t < cnt; t += gridDim.x) {
            int node = g_nbuck[grp][t];
            g_msg[(size_t)node*H + j] = 0.f;
        }
    }
}

// ---------------- per-level edge MLP (2 layers): h2 = relu(W2 relu(t1[g] + hf@W1b) + b2); msg += h2 ----------------
#define ETILE 32
__global__ void __launch_bounds__(128) emlp_k(
    int level, const int* __restrict__ ei, const int* __restrict__ gate,
    const float* __restrict__ w1,
    const float* __restrict__ w2, const float* __restrict__ b2,
    const float* __restrict__ nodes)
{
    __shared__ __align__(16) float sx[ETILE*H];
    __shared__ __align__(16) float sh1[ETILE*H];
    __shared__ int ssrc[ETILE];
    __shared__ int sdst[ETILE];
    __shared__ int sgate[ETILE];
    const int j  = threadIdx.x;
    const int gi = blockIdx.y;
    const int grp  = level*3 + gi;
    const int cnt  = g_ecnt[grp];
    const int ntile = (cnt + ETILE - 1) / ETILE;
    const float* hf  = nodes + NH;
    const float* W1b = w1 + (size_t)gi*2*H*H + (size_t)H*H;   // hf rows 128..255
    const float* W2  = w2 + (size_t)gi*H*H;
    const float  B2  = b2[gi*H + j];
    const float* T1  = g_t1 + gi*6*H;

    for (int tile = blockIdx.x; tile < ntile; tile += gridDim.x) {
        const int base = tile * ETILE;
        const int ne = min(ETILE, cnt - base);
        if (j < ETILE) {
            int e = g_ebuck[grp][base + (j < ne ? j : 0)];
            int s = ei[e];
            ssrc[j]  = s;
            sdst[j]  = ei[EE + e];
            sgate[j] = gate[s];
        }
        __syncthreads();
        #pragma unroll
        for (int t = 0; t < ETILE; t++)
            sx[t*H + j] = hf[(size_t)ssrc[t]*H + j];
        __syncthreads();

        float acc[ETILE];
        // layer 1 (hf part only; hs part is the t1 table, includes b1)
        #pragma unroll
        for (int t = 0; t < ETILE; t++) acc[t] = T1[sgate[t]*H + j];
        for (int k = 0; k < H; k += 4) {
            float wa = W1b[(k+0)*H + j];
            float wb = W1b[(k+1)*H + j];
            float wc = W1b[(k+2)*H + j];
            float wd = W1b[(k+3)*H + j];
            #pragma unroll
            for (int t = 0; t < ETILE; t++) {
                float4 xv = *reinterpret_cast<const float4*>(&sx[t*H + k]);
                acc[t] = fmaf(xv.x, wa, acc[t]);
                acc[t] = fmaf(xv.y, wb, acc[t]);
                acc[t] = fmaf(xv.z, wc, acc[t]);
                acc[t] = fmaf(xv.w, wd, acc[t]);
            }
        }
        #pragma unroll
        for (int t = 0; t < ETILE; t++) sh1[t*H + j] = fmaxf(acc[t], 0.f);
        __syncthreads();

        // layer 2
        #pragma unroll
        for (int t = 0; t < ETILE; t++) acc[t] = B2;
        for (int k = 0; k < H; k += 4) {
            float wa = W2[(k+0)*H + j];
            float wb = W2[(k+1)*H + j];
            float wc = W2[(k+2)*H + j];
            float wd = W2[(k+3)*H + j];
            #pragma unroll
            for (int t = 0; t < ETILE; t++) {
                float4 xv = *reinterpret_cast<const float4*>(&sh1[t*H + k]);
                acc[t] = fmaf(xv.x, wa, acc[t]);
                acc[t] = fmaf(xv.y, wb, acc[t]);
                acc[t] = fmaf(xv.z, wc, acc[t]);
                acc[t] = fmaf(xv.w, wd, acc[t]);
            }
        }
        // relu(h2) scatter-add
        for (int t = 0; t < ne; t++)
            atomicAdd(&g_msg[(size_t)sdst[t]*H + j], fmaxf(acc[t], 0.f));
        __syncthreads();
    }
}

// ---------------- per-level GRU: gin = H2sum@W4 + deg*c3 + bih; gh = bhh (h_old==0) ----------------
#define NTILE 16
__global__ void __launch_bounds__(128) gru_k(
    int level,
    const float* __restrict__ bih, const float* __restrict__ bhh,
    float* __restrict__ hfout)
{
    __shared__ __align__(16) float sm[NTILE*H];
    __shared__ int snode[NTILE];
    __shared__ int sdeg[NTILE];
    const int j  = threadIdx.x;
    const int gi = blockIdx.y;
    const int grp  = level*3 + gi;
    const int cnt  = g_ncnt[grp];
    const int ntile = (cnt + NTILE - 1) / NTILE;
    const float* WT = g_W4[gi];   // [k][384]
    const float br = bih[gi*384 + j]       + bhh[gi*384 + j];
    const float bz = bih[gi*384 + 128 + j] + bhh[gi*384 + 128 + j];
    const float bn = bih[gi*384 + 256 + j];
    const float hn = bhh[gi*384 + 256 + j];
    const float c3r = g_c3[gi*384 + j];
    const float c3z = g_c3[gi*384 + 128 + j];
    const float c3n = g_c3[gi*384 + 256 + j];

    for (int tile = blockIdx.x; tile < ntile; tile += gridDim.x) {
        const int base = tile * NTILE;
        const int nn = min(NTILE, cnt - base);
        if (j < NTILE) {
            int node = g_nbuck[grp][base + (j < nn ? j : 0)];
            snode[j] = node;
            sdeg[j]  = g_deg[node];
        }
        __syncthreads();
        #pragma unroll
        for (int t = 0; t < NTILE; t++) sm[t*H + j] = g_msg[(size_t)snode[t]*H + j];
        __syncthreads();

        float ar[NTILE], az[NTILE], an[NTILE];
        #pragma unroll
        for (int t = 0; t < NTILE; t++) { ar[t] = 0.f; az[t] = 0.f; an[t] = 0.f; }
        for (int k = 0; k < H; k += 2) {
            float wr0 = WT[(k+0)*384 + j];
            float wz0 = WT[(k+0)*384 + 128 + j];
            float wn0 = WT[(k+0)*384 + 256 + j];
            float wr1 = WT[(k+1)*384 + j];
            float wz1 = WT[(k+1)*384 + 128 + j];
            float wn1 = WT[(k+1)*384 + 256 + j];
            #pragma unroll
            for (int t = 0; t < NTILE; t++) {
                float2 mv = *reinterpret_cast<const float2*>(&sm[t*H + k]);
                ar[t] = fmaf(mv.x, wr0, ar[t]);
                az[t] = fmaf(mv.x, wz0, az[t]);
                an[t] = fmaf(mv.x, wn0, an[t]);
                ar[t] = fmaf(mv.y, wr1, ar[t]);
                az[t] = fmaf(mv.y, wz1, az[t]);
                an[t] = fmaf(mv.y, wn1, an[t]);
            }
        }
        #pragma unroll
        for (int t = 0; t < NTILE; t++) {
            if (t < nn) {
                float dg = (float)sdeg[t];
                float r = 1.f / (1.f + expf(-(ar[t] + br + dg*c3r)));
                float z = 1.f / (1.f + expf(-(az[t] + bz + dg*c3z)));
                float nst = tanhf(an[t] + bn + dg*c3n + r * hn);
                hfout[(size_t)snode[t]*H + j] = (1.f - z) * nst;
            }
        }
        __syncthreads();
    }
}

// ---------------- launch ----------------
extern "C" void kernel_launch(void* const* d_in, const int* in_sizes, int n_in,
                              void* d_out, int out_size) {
    const int*   gate = (const int*)d_in[0];
    const int*   lvl  = (const int*)d_in[1];
    const int*   ei   = (const int*)d_in[2];
    const float* Ws   = (const float*)d_in[3];
    const float* Wt   = (const float*)d_in[4];
    const float* hsW  = (const float*)d_in[5];
    const float* hsb  = (const float*)d_in[6];
    const float* w1   = (const float*)d_in[7];
    const float* b1   = (const float*)d_in[8];
    const float* w2   = (const float*)d_in[9];
    const float* b2   = (const float*)d_in[10];
    const float* w3   = (const float*)d_in[11];
    const float* b3   = (const float*)d_in[12];
    const float* wih  = (const float*)d_in[13];
    // d_in[14] = gru_whh: provably unused (h_old == 0 for every updated node)
    const float* bih  = (const float*)d_in[15];
    const float* bhh  = (const float*)d_in[16];
    float* out = (float*)d_out;   // [0, NH) = hs, [NH, 2NH) = hf

    zcnt_k<<<1, 32>>>();
    hs_type_k<<<6, 128>>>(Ws, Wt, hsW, hsb);
    t1_k<<<dim3(6, 3), 128>>>(w1, b1);
    w3T_k<<<(3*H*H + 255)/256, 256>>>(w3);
    w4_k<<<dim3(48, 3), 128>>>(wih);
    c3_k<<<3, 384>>>(b3, wih);
    scatter_k<<<2048, 128>>>(gate, out);
    bedge_k<<<512, 256>>>(ei, gate, lvl);
    bnode_k<<<256, 256>>>(gate, lvl);
    zmsg_k<<<2048, 128>>>();

    for (int level = 1; level < 8; level++) {
        emlp_k<<<dim3(160, 3), 128>>>(level, ei, gate, w1, w2, b2, out);
        gru_k<<<dim3(160, 3), 128>>>(level, bih, bhh, out + NH);
    }
}

// round 7
// speedup vs baseline: 2.4592x; 1.1326x over previous
#include <cuda_runtime.h>
#include <math.h>

#define NN 100000
#define EE 200000
#define H 128
#define NH (NN*H)
#define NGROUP 24   // 8 levels x 3 gate types (level 0 unused)

typedef unsigned long long u64;

// packed f32x2 helpers (Blackwell FFMA2 path)
#define FMA2(d, a, b) asm("fma.rn.f32x2 %0, %1, %2, %0;" : "+l"(d) : "l"(a), "l"(b))
__device__ __forceinline__ u64 pk2(float lo, float hi) {
    u64 r; asm("mov.b64 %0, {%1, %2};" : "=l"(r) : "f"(lo), "f"(hi)); return r;
}
__device__ __forceinline__ void upk2(u64 v, float& lo, float& hi) {
    asm("mov.b64 {%0, %1}, %2;" : "=f"(lo), "=f"(hi) : "l"(v));
}

// ---------------- scratch (static device memory; no allocs) ----------------
__device__ float g_msg[NN*H];            // h2 accumulator (zero at load; bucket rows re-zeroed per replay)
__device__ float g_hstype[6*H];
__device__ float g_t1[3*6*H];            // t1[gi][g] = hstype[g]@W1a + b1
__device__ float g_w3T[3][H*H];
__device__ float g_W4[3][H*384];         // W4 = W3 @ wih^T, k-major [k][m]
__device__ float g_c3[3*384];            // c3 = b3 @ wih^T
__device__ int   g_deg[NN];
__device__ int   g_ecnt[NGROUP];
__device__ int   g_ncnt[NGROUP];
__device__ int   g_ebuck[NGROUP][EE];
__device__ int   g_nbuck[NGROUP][NN];

// ---------------- setup kernels ----------------
__global__ void zcnt_k() {
    int t = threadIdx.x;
    if (t < NGROUP) { g_ecnt[t] = 0; g_ncnt[t] = 0; }
}

__global__ void hs_type_k(const float* __restrict__ Ws, const float* __restrict__ Wt,
                          const float* __restrict__ hsW, const float* __restrict__ hsb) {
    int g = blockIdx.x, j = threadIdx.x;
    __shared__ float st[256];
    st[j]       = Ws[g*H + j];
    st[128 + j] = Wt[g*H + j];
    __syncthreads();
    float acc = hsb[j];
    #pragma unroll 8
    for (int k = 0; k < 256; k++) acc = fmaf(st[k], hsW[k*H + j], acc);
    g_hstype[g*H + j] = acc;
}

__global__ void t1_k(const float* __restrict__ w1, const float* __restrict__ b1) {
    int g = blockIdx.x, gi = blockIdx.y, j = threadIdx.x;
    __shared__ float sh[H];
    sh[j] = g_hstype[g*H + j];
    __syncthreads();
    float acc = b1[gi*H + j];
    const float* W = w1 + (size_t)gi*2*H*H;
    #pragma unroll 8
    for (int k = 0; k < H; k++) acc = fmaf(sh[k], W[k*H + j], acc);
    g_t1[(gi*6 + g)*H + j] = acc;
}

__global__ void w3T_k(const float* __restrict__ w3) {
    int idx = blockIdx.x*blockDim.x + threadIdx.x;
    if (idx >= 3*H*H) return;
    int gi = idx / (H*H);
    int r  = idx % (H*H);
    int k = r / H, j = r % H;
    g_w3T[gi][j*H + k] = w3[(size_t)gi*H*H + k*H + j];
}

__global__ void w4_k(const float* __restrict__ wih) {
    int gi = blockIdx.y;
    int m0 = blockIdx.x * 8;
    int k  = threadIdx.x;
    __shared__ float sw[8][H];
    #pragma unroll
    for (int mm = 0; mm < 8; mm++) sw[mm][k] = wih[((size_t)gi*384 + m0 + mm)*H + k];
    __syncthreads();
    float acc[8];
    #pragma unroll
    for (int mm = 0; mm < 8; mm++) acc[mm] = 0.f;
    for (int j = 0; j < H; j++) {
        float v = g_w3T[gi][j*H + k];
        #pragma unroll
        for (int mm = 0; mm < 8; mm++) acc[mm] = fmaf(v, sw[mm][j], acc[mm]);
    }
    #pragma unroll
    for (int mm = 0; mm < 8; mm++) g_W4[gi][k*384 + m0 + mm] = acc[mm];
}

__global__ void c3_k(const float* __restrict__ b3, const float* __restrict__ wih) {
    int gi = blockIdx.x, m = threadIdx.x;
    __shared__ float sb[H];
    if (m < H) sb[m] = b3[gi*H + m];
    __syncthreads();
    float acc = 0.f;
    for (int j = 0; j < H; j++) acc = fmaf(sb[j], wih[((size_t)gi*384 + m)*H + j], acc);
    g_c3[gi*384 + m] = acc;
}

__global__ void scatter_k(const int* __restrict__ gate, float* __restrict__ out) {
    int j = threadIdx.x;
    int r = j >> 5, c = j & 31;
    float4* out4 = (float4*)out;
    const float4* ht4 = (const float4*)g_hstype;
    float4 z4 = make_float4(0.f, 0.f, 0.f, 0.f);
    for (int i0 = blockIdx.x*4; i0 < NN; i0 += gridDim.x*4) {
        int i = i0 + r;
        if (i < NN) {
            int g = gate[i];
            out4[(size_t)i*32 + c]        = ht4[g*32 + c];
            out4[(size_t)(NN + i)*32 + c] = z4;
        }
    }
    for (int i = blockIdx.x*blockDim.x + j; i < NN; i += gridDim.x*blockDim.x)
        g_deg[i] = 0;
}

__device__ __forceinline__ int gate_to_gi(int g) {
    // GATE_CODES = (3, 2, 5)
    return (g == 3) ? 0 : (g == 2) ? 1 : (g == 5) ? 2 : -1;
}

__global__ void bedge_k(const int* __restrict__ ei, const int* __restrict__ gate,
                        const int* __restrict__ lvl) {
    for (int e = blockIdx.x*blockDim.x + threadIdx.x; e < EE; e += gridDim.x*blockDim.x) {
        int d = ei[EE + e];
        int gi = gate_to_gi(gate[d]);
        int l = lvl[d];
        if (gi >= 0 && l >= 1) {
            int grp = l*3 + gi;
            int p = atomicAdd(&g_ecnt[grp], 1);
            g_ebuck[grp][p] = e;
            atomicAdd(&g_deg[d], 1);
        }
    }
}

__global__ void bnode_k(const int* __restrict__ gate, const int* __restrict__ lvl) {
    for (int i = blockIdx.x*blockDim.x + threadIdx.x; i < NN; i += gridDim.x*blockDim.x) {
        int gi = gate_to_gi(gate[i]);
        int l = lvl[i];
        if (gi >= 0 && l >= 1) {
            int grp = l*3 + gi;
            int p = atomicAdd(&g_ncnt[grp], 1);
            g_nbuck[grp][p] = i;
        }
    }
}

__global__ void zmsg_k() {
    int j = threadIdx.x;
    for (int grp = 0; grp < NGROUP; grp++) {
        int cnt = g_ncnt[grp];
        for (int t = blockIdx.x; t < cnt; t += gridDim.x) {
            int node = g_nbuck[grp][t];
            g_msg[(size_t)node*H + j] = 0.f;
        }
    }
}

// ---------------- per-level edge MLP (FFMA2 over k-pairs, ETILE=16) ----------------
#define ETILE 16
__global__ void __launch_bounds__(128) emlp_k(
    int level, const int* __restrict__ ei, const int* __restrict__ gate,
    const float* __restrict__ w1,
    const float* __restrict__ w2, const float* __restrict__ b2,
    const float* __restrict__ nodes)
{
    __shared__ __align__(16) float sx[ETILE*H];
    __shared__ __align__(16) float sh1[ETILE*H];
    __shared__ int ssrc[ETILE];
    __shared__ int sdst[ETILE];
    __shared__ int sgate[ETILE];
    const int j  = threadIdx.x;
    const int gi = blockIdx.y;
    const int grp  = level*3 + gi;
    const int cnt  = g_ecnt[grp];
    const int ntile = (cnt + ETILE - 1) / ETILE;
    const float* hf  = nodes + NH;
    const float* W1b = w1 + (size_t)gi*2*H*H + (size_t)H*H;   // hf rows 128..255
    const float* W2  = w2 + (size_t)gi*H*H;
    const float  B2  = b2[gi*H + j];
    const float* T1  = g_t1 + gi*6*H;

    for (int tile = blockIdx.x; tile < ntile; tile += gridDim.x) {
        const int base = tile * ETILE;
        const int ne = min(ETILE, cnt - base);
        if (j < ETILE) {
            int e = g_ebuck[grp][base + (j < ne ? j : 0)];
            int s = ei[e];
            ssrc[j]  = s;
            sdst[j]  = ei[EE + e];
            sgate[j] = gate[s];
        }
        __syncthreads();
        #pragma unroll
        for (int t = 0; t < ETILE; t++)
            sx[t*H + j] = hf[(size_t)ssrc[t]*H + j];
        __syncthreads();

        u64 acc[ETILE];
        // layer 1 (hf part; hs part + b1 are the t1 table). lo lane = even k, hi = odd k.
        #pragma unroll
        for (int t = 0; t < ETILE; t++) acc[t] = pk2(T1[sgate[t]*H + j], 0.f);
        for (int k = 0; k < H; k += 4) {
            u64 w01 = pk2(W1b[(k+0)*H + j], W1b[(k+1)*H + j]);
            u64 w23 = pk2(W1b[(k+2)*H + j], W1b[(k+3)*H + j]);
            #pragma unroll
            for (int t = 0; t < ETILE; t++) {
                ulonglong2 xv = *reinterpret_cast<const ulonglong2*>(&sx[t*H + k]);
                FMA2(acc[t], xv.x, w01);
                FMA2(acc[t], xv.y, w23);
            }
        }
        #pragma unroll
        for (int t = 0; t < ETILE; t++) {
            float lo, hi; upk2(acc[t], lo, hi);
            sh1[t*H + j] = fmaxf(lo + hi, 0.f);
        }
        __syncthreads();

        // layer 2
        #pragma unroll
        for (int t = 0; t < ETILE; t++) acc[t] = pk2(B2, 0.f);
        for (int k = 0; k < H; k += 4) {
            u64 w01 = pk2(W2[(k+0)*H + j], W2[(k+1)*H + j]);
            u64 w23 = pk2(W2[(k+2)*H + j], W2[(k+3)*H + j]);
            #pragma unroll
            for (int t = 0; t < ETILE; t++) {
                ulonglong2 xv = *reinterpret_cast<const ulonglong2*>(&sh1[t*H + k]);
                FMA2(acc[t], xv.x, w01);
                FMA2(acc[t], xv.y, w23);
            }
        }
        // relu(h2) scatter-add
        for (int t = 0; t < ne; t++) {
            float lo, hi; upk2(acc[t], lo, hi);
            atomicAdd(&g_msg[(size_t)sdst[t]*H + j], fmaxf(lo + hi, 0.f));
        }
        __syncthreads();
    }
}

// ---------------- per-level GRU (FFMA2 over t-pairs via transposed smem) ----------------
#define NTILE 16
#define MST 18   // padded row stride (words) -> u64 reads stay 8B-aligned, fill 2-way conflict only
__global__ void __launch_bounds__(128) gru_k(
    int level,
    const float* __restrict__ bih, const float* __restrict__ bhh,
    float* __restrict__ hfout)
{
    __shared__ __align__(16) float smt[H*MST];   // smt[k*MST + t] = msg[node[t]][k]
    __shared__ int snode[NTILE];
    __shared__ int sdeg[NTILE];
    const int j  = threadIdx.x;
    const int gi = blockIdx.y;
    const int grp  = level*3 + gi;
    const int cnt  = g_ncnt[grp];
    const int ntile = (cnt + NTILE - 1) / NTILE;
    const float* WT = g_W4[gi];   // [k][384]
    const float br = bih[gi*384 + j]       + bhh[gi*384 + j];
    const float bz = bih[gi*384 + 128 + j] + bhh[gi*384 + 128 + j];
    const float bn = bih[gi*384 + 256 + j];
    const float hn = bhh[gi*384 + 256 + j];
    const float c3r = g_c3[gi*384 + j];
    const float c3z = g_c3[gi*384 + 128 + j];
    const float c3n = g_c3[gi*384 + 256 + j];

    for (int tile = blockIdx.x; tile < ntile; tile += gridDim.x) {
        const int base = tile * NTILE;
        const int nn = min(NTILE, cnt - base);
        if (j < NTILE) {
            int node = g_nbuck[grp][base + (j < nn ? j : 0)];
            snode[j] = node;
            sdeg[j]  = g_deg[node];
        }
        __syncthreads();
        // transposed fill: thread j owns k=j row
        #pragma unroll
        for (int t = 0; t < NTILE; t++)
            smt[j*MST + t] = g_msg[(size_t)snode[t]*H + j];
        __syncthreads();

        u64 ar[NTILE/2], az[NTILE/2], an[NTILE/2];
        #pragma unroll
        for (int p = 0; p < NTILE/2; p++) { ar[p] = 0ull; az[p] = 0ull; an[p] = 0ull; }
        #pragma unroll 2
        for (int k = 0; k < H; k++) {
            float wr = WT[k*384 + j];
            float wz = WT[k*384 + 128 + j];
            float wn = WT[k*384 + 256 + j];
            u64 wr2 = pk2(wr, wr), wz2 = pk2(wz, wz), wn2 = pk2(wn, wn);
            #pragma unroll
            for (int p = 0; p < NTILE/2; p++) {
                u64 x = *reinterpret_cast<const u64*>(&smt[k*MST + 2*p]);  // broadcast
                FMA2(ar[p], x, wr2);
                FMA2(az[p], x, wz2);
                FMA2(an[p], x, wn2);
            }
        }
        #pragma unroll
        for (int p = 0; p < NTILE/2; p++) {
            float arA, arB, azA, azB, anA, anB;
            upk2(ar[p], arA, arB);
            upk2(az[p], azA, azB);
            upk2(an[p], anA, anB);
            int t0 = 2*p, t1 = 2*p + 1;
            if (t0 < nn) {
                float dg = (float)sdeg[t0];
                float r = 1.f / (1.f + expf(-(arA + br + dg*c3r)));
                float z = 1.f / (1.f + expf(-(azA + bz + dg*c3z)));
                float nst = tanhf(anA + bn + dg*c3n + r * hn);
                hfout[(size_t)snode[t0]*H + j] = (1.f - z) * nst;
            }
            if (t1 < nn) {
                float dg = (float)sdeg[t1];
                float r = 1.f / (1.f + expf(-(arB + br + dg*c3r)));
                float z = 1.f / (1.f + expf(-(azB + bz + dg*c3z)));
                float nst = tanhf(anB + bn + dg*c3n + r * hn);
                hfout[(size_t)snode[t1]*H + j] = (1.f - z) * nst;
            }
        }
        __syncthreads();
    }
}

// ---------------- launch ----------------
extern "C" void kernel_launch(void* const* d_in, const int* in_sizes, int n_in,
                              void* d_out, int out_size) {
    const int*   gate = (const int*)d_in[0];
    const int*   lvl  = (const int*)d_in[1];
    const int*   ei   = (const int*)d_in[2];
    const float* Ws   = (const float*)d_in[3];
    const float* Wt   = (const float*)d_in[4];
    const float* hsW  = (const float*)d_in[5];
    const float* hsb  = (const float*)d_in[6];
    const float* w1   = (const float*)d_in[7];
    const float* b1   = (const float*)d_in[8];
    const float* w2   = (const float*)d_in[9];
    const float* b2   = (const float*)d_in[10];
    const float* w3   = (const float*)d_in[11];
    const float* b3   = (const float*)d_in[12];
    const float* wih  = (const float*)d_in[13];
    // d_in[14] = gru_whh: provably unused (h_old == 0 for every updated node)
    const float* bih  = (const float*)d_in[15];
    const float* bhh  = (const float*)d_in[16];
    float* out = (float*)d_out;   // [0, NH) = hs, [NH, 2NH) = hf

    zcnt_k<<<1, 32>>>();
    hs_type_k<<<6, 128>>>(Ws, Wt, hsW, hsb);
    t1_k<<<dim3(6, 3), 128>>>(w1, b1);
    w3T_k<<<(3*H*H + 255)/256, 256>>>(w3);
    w4_k<<<dim3(48, 3), 128>>>(wih);
    c3_k<<<3, 384>>>(b3, wih);
    scatter_k<<<2048, 128>>>(gate, out);
    bedge_k<<<512, 256>>>(ei, gate, lvl);
    bnode_k<<<256, 256>>>(gate, lvl);
    zmsg_k<<<2048, 128>>>();

    for (int level = 1; level < 8; level++) {
        emlp_k<<<dim3(288, 3), 128>>>(level, ei, gate, w1, w2, b2, out);
        gru_k<<<dim3(144, 3), 128>>>(level, bih, bhh, out + NH);
    }
}